// round 1
// baseline (speedup 1.0000x reference)
#include <cuda_runtime.h>
#include <cuda_bf16.h>

#define BINS 30
#define TPB  128
#define GRID 592   // 148 SMs * 4 blocks, one wave at 30KB smem/block

__device__ float g_counts[BINS];
__device__ float g_cesum[BINS];

__global__ void ghm_zero() {
    int i = threadIdx.x;
    if (i < BINS) { g_counts[i] = 0.0f; g_cesum[i] = 0.0f; }
}

__device__ __forceinline__ void ghm_elem(float x0, float x1, int t, float2* hrow) {
    float m  = fmaxf(x0, x1);
    float mn = fminf(x0, x1);
    bool  t1 = (t != 0);
    float xt = t1 ? x1 : x0;
    float xo = t1 ? x0 : x1;
    float e  = __expf(mn - m);          // exp of (smaller - larger); exp(0)=1 handled below
    float s  = 1.0f + e;
    float et = (xt >= xo) ? 1.0f : e;   // e_true = exp(x_t - m)
    float pt = __fdividef(et, s);
    float g  = fabsf(pt - 1.0f);
    int bin  = (int)(g * 30.0f);
    bin = bin > (BINS - 1) ? (BINS - 1) : bin;   // g >= 0 so no lower clamp
    float ce = (m - xt) + __logf(s);

    float2 h = hrow[bin * TPB];
    h.x += 1.0f;
    h.y += ce;
    hrow[bin * TPB] = h;
}

__global__ void __launch_bounds__(TPB) ghm_hist(const float2* __restrict__ x,
                                                const int* __restrict__ tgt,
                                                int B) {
    __shared__ float2 hist[BINS * TPB];   // hist[bin*TPB + tid] -> bank-conflict-free
    int tid = threadIdx.x;

    #pragma unroll
    for (int b = 0; b < BINS; b++) hist[b * TPB + tid] = make_float2(0.0f, 0.0f);
    __syncthreads();

    float2* hrow = &hist[tid];

    int gt = blockIdx.x * TPB + tid;
    int nthreads = gridDim.x * TPB;
    int ngroups = B >> 2;                 // groups of 4 elements

    const float4* x4 = (const float4*)x;  // 2 elements per float4
    const int4*   t4 = (const int4*)tgt;

    for (int grp = gt; grp < ngroups; grp += nthreads) {
        float4 a = x4[grp * 2];
        float4 b = x4[grp * 2 + 1];
        int4   tt = t4[grp];
        ghm_elem(a.x, a.y, tt.x, hrow);
        ghm_elem(a.z, a.w, tt.y, hrow);
        ghm_elem(b.x, b.y, tt.z, hrow);
        ghm_elem(b.z, b.w, tt.w, hrow);
    }
    // scalar tail (B % 4 != 0)
    int tail_start = ngroups << 2;
    for (int j = tail_start + gt; j < B; j += nthreads) {
        float2 xv = x[j];
        ghm_elem(xv.x, xv.y, tgt[j], hrow);
    }

    __syncthreads();

    // tree-reduce across threads for each bin
    for (int s = TPB / 2; s > 0; s >>= 1) {
        if (tid < s) {
            #pragma unroll
            for (int b = 0; b < BINS; b++) {
                float2 a = hist[b * TPB + tid];
                float2 c = hist[b * TPB + tid + s];
                a.x += c.x; a.y += c.y;
                hist[b * TPB + tid] = a;
            }
        }
        __syncthreads();
    }

    if (tid < BINS) {
        atomicAdd(&g_counts[tid], hist[tid * TPB].x);
        atomicAdd(&g_cesum[tid],  hist[tid * TPB].y);
    }
}

__global__ void ghm_final(float* __restrict__ out, int out_size) {
    int lane = threadIdx.x;
    float cnt = (lane < BINS) ? g_counts[lane] : 0.0f;
    float ces = (lane < BINS) ? g_cesum[lane]  : 0.0f;
    float nz   = (cnt > 0.0f) ? 1.0f : 0.0f;
    float term = (cnt > 0.0f) ? ces / (0.25f * cnt) : 0.0f;
    #pragma unroll
    for (int o = 16; o > 0; o >>= 1) {
        nz   += __shfl_xor_sync(0xFFFFFFFFu, nz,   o);
        term += __shfl_xor_sync(0xFFFFFFFFu, term, o);
    }
    if (lane == 0) {
        float loss = term / fmaxf(nz, 1.0f);
        for (int i = 0; i < out_size; i++) out[i] = loss;
    }
}

extern "C" void kernel_launch(void* const* d_in, const int* in_sizes, int n_in,
                              void* d_out, int out_size) {
    const float* x   = (const float*)d_in[0];
    const int*   tgt = (const int*)d_in[1];
    int B = in_sizes[1];   // target element count == batch size

    ghm_zero<<<1, 32>>>();
    ghm_hist<<<GRID, TPB>>>((const float2*)x, tgt, B);
    ghm_final<<<1, 32>>>((float*)d_out, out_size);
}